// round 9
// baseline (speedup 1.0000x reference)
#include <cuda_runtime.h>
#include <cuda_bf16.h>
#include <math.h>
#include <stdint.h>

// ---------------- problem constants ----------------
#define D        1024
#define E        8
#define MOED     2048
#define MAXROWS  16384
#define PADROWS  (MAXROWS + 256)
#define MAXCNT   4096      // per-expert row bound (mean 2048, sigma ~42)

#define BK       16        // k elems per pipeline stage
#define ARS      48        // A smem row stride (16 bf16 = 32B + 16 pad)
#define BRS      272       // B smem row stride (128 bf16 = 256B + 16 pad)
#define AH_OFF   0
#define AL_OFF   6144
#define BH_OFF   12288
#define BL_OFF   16640
#define STAGE    20992
#define SM_BYTES (2 * STAGE)   // 41984 <= 48K static limit

// ---------------- device scratch (proven ~137 MB budget) ----------------
__device__ int   g_count[E];
__device__ int   g_offset[E];
__device__ int   g_tokens[E][MAXROWS];
__device__ float g_weights[E][MAXROWS];
__device__ __align__(256) __nv_bfloat16 g_hid_hi[(size_t)PADROWS * MOED];
__device__ __align__(256) __nv_bfloat16 g_hid_lo[(size_t)PADROWS * MOED];

// ---------------- helpers ----------------
__device__ __forceinline__ uint32_t smem_u32(const void* p) {
    uint32_t a;
    asm("{ .reg .u64 t; cvta.to.shared.u64 t, %1; cvt.u32.u64 %0, t; }" : "=r"(a) : "l"(p));
    return a;
}
__device__ __forceinline__ void ldsm4(uint32_t* r, uint32_t addr) {
    asm volatile("ldmatrix.sync.aligned.m8n8.x4.shared.b16 {%0,%1,%2,%3}, [%4];"
        : "=r"(r[0]), "=r"(r[1]), "=r"(r[2]), "=r"(r[3]) : "r"(addr));
}
__device__ __forceinline__ void ldsm4t(uint32_t* r, uint32_t addr) {
    asm volatile("ldmatrix.sync.aligned.m8n8.x4.trans.shared.b16 {%0,%1,%2,%3}, [%4];"
        : "=r"(r[0]), "=r"(r[1]), "=r"(r[2]), "=r"(r[3]) : "r"(addr));
}
__device__ __forceinline__ void mma16816(float* c, const uint32_t* a, uint32_t b0, uint32_t b1) {
    asm volatile("mma.sync.aligned.m16n8k16.row.col.f32.bf16.bf16.f32 "
        "{%0,%1,%2,%3}, {%4,%5,%6,%7}, {%8,%9}, {%0,%1,%2,%3};"
        : "+f"(c[0]), "+f"(c[1]), "+f"(c[2]), "+f"(c[3])
        : "r"(a[0]), "r"(a[1]), "r"(a[2]), "r"(a[3]), "r"(b0), "r"(b1));
}
__device__ __forceinline__ uint32_t pack2(float a, float b, uint32_t& lo) {
    __nv_bfloat16 ha = __float2bfloat16(a);
    __nv_bfloat16 hb = __float2bfloat16(b);
    __nv_bfloat16 la = __float2bfloat16(a - __bfloat162float(ha));
    __nv_bfloat16 lb = __float2bfloat16(b - __bfloat162float(hb));
    lo = (uint32_t)__bfloat16_as_ushort(la) | ((uint32_t)__bfloat16_as_ushort(lb) << 16);
    return (uint32_t)__bfloat16_as_ushort(ha) | ((uint32_t)__bfloat16_as_ushort(hb) << 16);
}
__device__ __forceinline__ void cvt8(float4 v0, float4 v1, uint4& hi, uint4& lo) {
    uint32_t l0, l1, l2, l3;
    uint32_t h0 = pack2(v0.x, v0.y, l0);
    uint32_t h1 = pack2(v0.z, v0.w, l1);
    uint32_t h2 = pack2(v1.x, v1.y, l2);
    uint32_t h3 = pack2(v1.z, v1.w, l3);
    hi = make_uint4(h0, h1, h2, h3);
    lo = make_uint4(l0, l1, l2, l3);
}

// ---------------- init ----------------
__global__ void init_kernel(float* __restrict__ out, int n) {
    int i = blockIdx.x * blockDim.x + threadIdx.x;
    if (i < E) g_count[i] = 0;
    for (; i < n; i += gridDim.x * blockDim.x) out[i] = 0.0f;
}

// ---------------- router (proven, verbatim) ----------------
__global__ void router_kernel(const float* __restrict__ x,
                              const float* __restrict__ router, int T) {
    __shared__ float s_r[D * E];
    __shared__ float s_logits[32][E];
    int tid = threadIdx.x;
    for (int i = tid; i < D * E; i += 256) s_r[i] = router[i];
    __syncthreads();

    int tl = tid >> 3;
    int e  = tid & 7;
    int t  = blockIdx.x * 32 + tl;
    float acc = 0.0f;
    if (t < T) {
        const float* xr = x + (size_t)t * D;
        #pragma unroll 8
        for (int k = 0; k < D; k++) acc = fmaf(xr[k], s_r[k * E + e], acc);
    }
    s_logits[tl][e] = acc;
    __syncthreads();

    if (tid < 32) {
        int t2 = blockIdx.x * 32 + tid;
        if (t2 < T) {
            float* L = s_logits[tid];
            int e0 = 0; float l0 = L[0];
            #pragma unroll
            for (int i = 1; i < E; i++) if (L[i] > l0) { l0 = L[i]; e0 = i; }
            int e1 = -1; float l1 = -INFINITY;
            #pragma unroll
            for (int i = 0; i < E; i++) {
                if (i == e0) continue;
                if (L[i] > l1) { l1 = L[i]; e1 = i; }
            }
            float w0 = 1.0f / (1.0f + expf(l1 - l0));
            float w1 = 1.0f - w0;
            int s0 = atomicAdd(&g_count[e0], 1);
            g_tokens[e0][s0]  = t2;
            g_weights[e0][s0] = w0;
            int s1 = atomicAdd(&g_count[e1], 1);
            g_tokens[e1][s1]  = t2;
            g_weights[e1][s1] = w1;
        }
    }
}

__global__ void offsets_kernel() {
    if (threadIdx.x == 0) {
        int s = 0;
        #pragma unroll
        for (int i = 0; i < E; i++) { g_offset[i] = s; s += g_count[i]; }
    }
}

// ---------------- GEMM1: 128m x (64 gate + 64 up), double-buffered BK=16 ------
__global__ void __launch_bounds__(256, 2) gemm1_kernel(const float* __restrict__ x,
                                                       const float* __restrict__ w13) {
    __shared__ __align__(16) char sm[SM_BYTES];
    __shared__ int s_tok[128];
    int e   = blockIdx.z;
    int cnt = g_count[e];
    int m0  = blockIdx.y * 128;
    if (m0 >= cnt) return;
    int n0  = blockIdx.x * 64;
    int off = g_offset[e];
    int tid = threadIdx.x, wid = tid >> 5, lane = tid & 31;

    if (tid < 128) {
        int m = m0 + tid;
        s_tok[tid] = g_tokens[e][(m < cnt) ? m : (cnt - 1)];
    }
    __syncthreads();

    int arow = tid >> 1, akh = tid & 1;
    const float* aptr = x + (size_t)s_tok[arow] * D + akh * 8;
    uint32_t a_sdst = (uint32_t)(arow * ARS + akh * 16);
    int brow = tid >> 4, bc = tid & 15;
    int c8 = bc * 8;
    int ncol = (c8 < 64) ? (n0 + c8) : (MOED + n0 + (c8 - 64));
    const float* bptr = w13 + ((size_t)e * D + brow) * (2 * MOED) + ncol;
    uint32_t b_sdst = (uint32_t)(BH_OFF + brow * BRS + bc * 16);

    float accg[2][4][4], accu[2][4][4];
    #pragma unroll
    for (int i = 0; i < 2; i++)
        #pragma unroll
        for (int j = 0; j < 4; j++)
            #pragma unroll
            for (int q = 0; q < 4; q++) { accg[i][j][q] = 0.0f; accu[i][j][q] = 0.0f; }

    int wm = wid >> 1, wn = wid & 1;
    int lr = lane & 15, lh16 = (lane >> 4) << 4;
    int btr = ((lane >> 3) & 1) * 8 + (lane & 7);
    uint32_t sb = smem_u32(sm);

    float4 stgA[2], stgB[2];
    stgA[0] = *reinterpret_cast<const float4*>(aptr);
    stgA[1] = *reinterpret_cast<const float4*>(aptr + 4);
    stgB[0] = *reinterpret_cast<const float4*>(bptr);
    stgB[1] = *reinterpret_cast<const float4*>(bptr + 4);
    {
        uint4 hi, lo;
        cvt8(stgA[0], stgA[1], hi, lo);
        *reinterpret_cast<uint4*>(sm + a_sdst) = hi;
        *reinterpret_cast<uint4*>(sm + a_sdst + AL_OFF) = lo;
        cvt8(stgB[0], stgB[1], hi, lo);
        *reinterpret_cast<uint4*>(sm + b_sdst) = hi;
        *reinterpret_cast<uint4*>(sm + b_sdst + (BL_OFF - BH_OFF)) = lo;
    }
    stgA[0] = *reinterpret_cast<const float4*>(aptr + BK);
    stgA[1] = *reinterpret_cast<const float4*>(aptr + BK + 4);
    stgB[0] = *reinterpret_cast<const float4*>(bptr + (size_t)BK * (2 * MOED));
    stgB[1] = *reinterpret_cast<const float4*>(bptr + (size_t)BK * (2 * MOED) + 4);
    __syncthreads();

    const int KT = D / BK;   // 64
    for (int kt = 0; kt < KT; kt++) {
        uint32_t bb = sb + (kt & 1) * STAGE;
        uint32_t aH = bb + (uint32_t)(wm * 32 + lr) * ARS + lh16;
        uint32_t aL = aH + AL_OFF;
        uint32_t bH = bb + BH_OFF + (uint32_t)btr * BRS + wn * 64 + lh16;
        uint32_t bL = bH + (BL_OFF - BH_OFF);

        // 1) issue current-stage ldsm FIRST (A + B half0)
        uint32_t ah[2][4], al[2][4];
        #pragma unroll
        for (int mi = 0; mi < 2; mi++) {
            ldsm4(ah[mi], aH + mi * (16 * ARS));
            ldsm4(al[mi], aL + mi * (16 * ARS));
        }
        uint32_t gh0[4], gl0[4], uh0[4], ul0[4];
        ldsm4t(gh0, bH);
        ldsm4t(gl0, bL);
        ldsm4t(uh0, bH + 128);
        ldsm4t(ul0, bL + 128);

        // 2) overlap: STS next stage + LDG stage+2
        int nbuf = (kt + 1) & 1;
        if (kt + 1 < KT) {
            uint4 hi, lo;
            cvt8(stgA[0], stgA[1], hi, lo);
            *reinterpret_cast<uint4*>(sm + nbuf * STAGE + a_sdst) = hi;
            *reinterpret_cast<uint4*>(sm + nbuf * STAGE + a_sdst + AL_OFF) = lo;
            cvt8(stgB[0], stgB[1], hi, lo);
            *reinterpret_cast<uint4*>(sm + nbuf * STAGE + b_sdst) = hi;
            *reinterpret_cast<uint4*>(sm + nbuf * STAGE + b_sdst + (BL_OFF - BH_OFF)) = lo;
        }
        if (kt + 2 < KT) {
            stgA[0] = *reinterpret_cast<const float4*>(aptr + (kt + 2) * BK);
            stgA[1] = *reinterpret_cast<const float4*>(aptr + (kt + 2) * BK + 4);
            stgB[0] = *reinterpret_cast<const float4*>(bptr + (size_t)(kt + 2) * BK * (2 * MOED));
            stgB[1] = *reinterpret_cast<const float4*>(bptr + (size_t)(kt + 2) * BK * (2 * MOED) + 4);
        }

        // 3) MMA half0
        #pragma unroll
        for (int r = 0; r < 2; r++) {
            #pragma unroll
            for (int mi = 0; mi < 2; mi++) {
                mma16816(accg[mi][r], ah[mi], gh0[2 * r], gh0[2 * r + 1]);
                mma16816(accg[mi][r], ah[mi], gl0[2 * r], gl0[2 * r + 1]);
                mma16816(accg[mi][r], al[mi], gh0[2 * r], gh0[2 * r + 1]);
                mma16816(accu[mi][r], ah[mi], uh0[2 * r], uh0[2 * r + 1]);
                mma16816(accu[mi][r], ah[mi], ul0[2 * r], ul0[2 * r + 1]);
                mma16816(accu[mi][r], al[mi], uh0[2 * r], uh0[2 * r + 1]);
            }
        }

        // 4) B half1 ldsm + MMA
        uint32_t gh1[4], gl1[4], uh1[4], ul1[4];
        ldsm4t(gh1, bH + 32);
        ldsm4t(gl1, bL + 32);
        ldsm4t(uh1, bH + 32 + 128);
        ldsm4t(ul1, bL + 32 + 128);
        #pragma unroll
        for (int r = 0; r < 2; r++) {
            int ni = 2 + r;
            #pragma unroll
            for (int mi = 0; mi < 2; mi++) {
                mma16816(accg[mi][ni], ah[mi], gh1[2 * r], gh1[2 * r + 1]);
                mma16816(accg[mi][ni], ah[mi], gl1[2 * r], gl1[2 * r + 1]);
                mma16816(accg[mi][ni], al[mi], gh1[2 * r], gh1[2 * r + 1]);
                mma16816(accu[mi][ni], ah[mi], uh1[2 * r], uh1[2 * r + 1]);
                mma16816(accu[mi][ni], ah[mi], ul1[2 * r], ul1[2 * r + 1]);
                mma16816(accu[mi][ni], al[mi], uh1[2 * r], uh1[2 * r + 1]);
            }
        }
        __syncthreads();
    }

    // epilogue: SwiGLU, split in-register, store bf16 hi/lo hidden
    #pragma unroll
    for (int mi = 0; mi < 2; mi++) {
        #pragma unroll
        for (int rr = 0; rr < 2; rr++) {
            int ml = wm * 32 + mi * 16 + (lane >> 2) + rr * 8;
            if (m0 + ml < cnt) {
                size_t rb = (size_t)(off + m0 + ml) * MOED + n0 + wn * 32;
                #pragma unroll
                for (int ni = 0; ni < 4; ni++) {
                    int nc = ni * 8 + (lane & 3) * 2;
                    float g0 = accg[mi][ni][rr * 2 + 0], g1 = accg[mi][ni][rr * 2 + 1];
                    float u0 = accu[mi][ni][rr * 2 + 0], u1 = accu[mi][ni][rr * 2 + 1];
                    float h0 = u0 * g0 / (1.0f + __expf(-g0));
                    float h1 = u1 * g1 / (1.0f + __expf(-g1));
                    uint32_t lo;
                    uint32_t hi = pack2(h0, h1, lo);
                    *reinterpret_cast<uint32_t*>(g_hid_hi + rb + nc) = hi;
                    *reinterpret_cast<uint32_t*>(g_hid_lo + rb + nc) = lo;
                }
            }
        }
    }
}

// ---------------- GEMM2: 128m x 128n, double-buffered BK=16 -------------------
__global__ void __launch_bounds__(256, 2) gemm2_kernel(const float* __restrict__ w2,
                                                       float* __restrict__ out) {
    __shared__ __align__(16) char sm[SM_BYTES];
    int e   = blockIdx.z;
    int cnt = g_count[e];
    int m0  = blockIdx.y * 128;
    if (m0 >= cnt) return;
    int n0  = blockIdx.x * 128;
    int off = g_offset[e];
    int tid = threadIdx.x, wid = tid >> 5, lane = tid & 31;

    int arow = tid >> 1, akh = tid & 1;
    const __nv_bfloat16* aH_src = g_hid_hi + (size_t)(off + m0 + arow) * MOED + akh * 8;
    const __nv_bfloat16* aL_src = g_hid_lo + (size_t)(off + m0 + arow) * MOED + akh * 8;
    uint32_t a_sdst = (uint32_t)(arow * ARS + akh * 16);
    int brow = tid >> 4, bc = tid & 15;
    const float* bptr = w2 + ((size_t)e * MOED + brow) * D + n0 + bc * 8;
    uint32_t b_sdst = (uint32_t)(BH_OFF + brow * BRS + bc * 16);

    float acc[2][8][4];
    #pragma unroll
    for (int i = 0; i < 2; i++)
        #pragma unroll
        for (int j = 0; j < 8; j++)
            #pragma unroll
            for (int q = 0; q < 4; q++) acc[i][j][q] = 0.0f;

    int wm = wid >> 1, wn = wid & 1;
    int lr = lane & 15, lh16 = (lane >> 4) << 4;
    int btr = ((lane >> 3) & 1) * 8 + (lane & 7);
    uint32_t sb = smem_u32(sm);

    uint4 stgAH, stgAL;
    float4 stgB[2];
    stgAH = *reinterpret_cast<const uint4*>(aH_src);
    stgAL = *reinterpret_cast<const uint4*>(aL_src);
    stgB[0] = *reinterpret_cast<const float4*>(bptr);
    stgB[1] = *reinterpret_cast<const float4*>(bptr + 4);
    {
        *reinterpret_cast<uint4*>(sm + a_sdst) = stgAH;
        *reinterpret_cast<uint4*>(sm + a_sdst + AL_OFF) = stgAL;
        uint4 hi, lo;
        cvt8(stgB[0], stgB[1], hi, lo);
        *reinterpret_cast<uint4*>(sm + b_sdst) = hi;
        *reinterpret_cast<uint4*>(sm + b_sdst + (BL_OFF - BH_OFF)) = lo;
    }
    stgAH = *reinterpret_cast<const uint4*>(aH_src + BK);
    stgAL = *reinterpret_cast<const uint4*>(aL_src + BK);
    stgB[0] = *reinterpret_cast<const float4*>(bptr + (size_t)BK * D);
    stgB[1] = *reinterpret_cast<const float4*>(bptr + (size_t)BK * D + 4);
    __syncthreads();

    const int KT = MOED / BK;   // 128
    for (int kt = 0; kt < KT; kt++) {
        uint32_t bb = sb + (kt & 1) * STAGE;
        uint32_t aH = bb + (uint32_t)(wm * 32 + lr) * ARS + lh16;
        uint32_t aL = aH + AL_OFF;
        uint32_t bH = bb + BH_OFF + (uint32_t)btr * BRS + wn * 128 + lh16;
        uint32_t bL = bH + (BL_OFF - BH_OFF);

        // 1) current-stage ldsm first: A + B halves 0,1
        uint32_t ah[2][4], al[2][4];
        #pragma unroll
        for (int mi = 0; mi < 2; mi++) {
            ldsm4(ah[mi], aH + mi * (16 * ARS));
            ldsm4(al[mi], aL + mi * (16 * ARS));
        }
        uint32_t bh0[4], bl0[4], bh1[4], bl1[4];
        ldsm4t(bh0, bH);
        ldsm4t(bl0, bL);
        ldsm4t(bh1, bH + 32);
        ldsm4t(bl1, bL + 32);

        // 2) overlap STS/LDG
        int nbuf = (kt + 1) & 1;
        if (kt + 1 < KT) {
            *reinterpret_cast<uint4*>(sm + nbuf * STAGE + a_sdst) = stgAH;
            *reinterpret_cast<uint4*>(sm + nbuf * STAGE + a_sdst + AL_OFF) = stgAL;
            uint4 hi, lo;
            cvt8(stgB[0], stgB[1], hi, lo);
            *reinterpret_cast<uint4*>(sm + nbuf * STAGE + b_sdst) = hi;
            *reinterpret_cast<uint4*>(sm + nbuf * STAGE + b_sdst + (BL_OFF - BH_OFF)) = lo;
        }
        if (kt + 2 < KT) {
            stgAH = *reinterpret_cast<const uint4*>(aH_src + (kt + 2) * BK);
            stgAL = *reinterpret_cast<const uint4*>(aL_src + (kt + 2) * BK);
            stgB[0] = *reinterpret_cast<const float4*>(bptr + (size_t)(kt + 2) * BK * D);
            stgB[1] = *reinterpret_cast<const float4*>(bptr + (size_t)(kt + 2) * BK * D + 4);
        }

        // 3) MMA half0, ldsm half2, MMA half1, ldsm half3, MMA half2+3
        #pragma unroll
        for (int r = 0; r < 2; r++)
            #pragma unroll
            for (int mi = 0; mi < 2; mi++) {
                mma16816(acc[mi][r], ah[mi], bh0[2 * r], bh0[2 * r + 1]);
                mma16816(acc[mi][r], ah[mi], bl0[2 * r], bl0[2 * r + 1]);
                mma16816(acc[mi][r], al[mi], bh0[2 * r], bh0[2 * r + 1]);
            }
        uint32_t bh2[4], bl2[4];
        ldsm4t(bh2, bH + 64);
        ldsm4t(bl2, bL + 64);
        #pragma unroll
        for (int r = 0; r < 2; r++)
            #pragma unroll
            for (int mi = 0; mi < 2; mi++) {
                mma16816(acc[mi][2 + r], ah[mi], bh1[2 * r], bh1[2 * r + 1]);
                mma16816(acc[mi][2 + r], ah[mi], bl1[2 * r], bl1[2 * r + 1]);
                mma16816(acc[mi][2 + r], al[mi], bh1[2 * r], bh1[2 * r + 1]);
            }
        uint32_t bh3[4], bl3[4];
        ldsm4t(bh3, bH + 96);
        ldsm4t(bl3, bL + 96);
        #pragma unroll
        for (int r = 0; r < 2; r++)
            #pragma unroll
            for (int mi = 0; mi < 2; mi++) {
                mma16816(acc[mi][4 + r], ah[mi], bh2[2 * r], bh2[2 * r + 1]);
                mma16816(acc[mi][4 + r], ah[mi], bl2[2 * r], bl2[2 * r + 1]);
                mma16816(acc[mi][4 + r], al[mi], bh2[2 * r], bh2[2 * r + 1]);
            }
        #pragma unroll
        for (int r = 0; r < 2; r++)
            #pragma unroll
            for (int mi = 0; mi < 2; mi++) {
                mma16816(acc[mi][6 + r], ah[mi], bh3[2 * r], bh3[2 * r + 1]);
                mma16816(acc[mi][6 + r], ah[mi], bl3[2 * r], bl3[2 * r + 1]);
                mma16816(acc[mi][6 + r], al[mi], bh3[2 * r], bh3[2 * r + 1]);
            }
        __syncthreads();
    }

    // epilogue: weighted scatter-add (exactly 2 adds per out element)
    #pragma unroll
    for (int mi = 0; mi < 2; mi++) {
        #pragma unroll
        for (int rr = 0; rr < 2; rr++) {
            int ml = wm * 32 + mi * 16 + (lane >> 2) + rr * 8;
            if (m0 + ml < cnt) {
                int   t = g_tokens[e][m0 + ml];
                float w = g_weights[e][m0 + ml];
                float* orow = out + (size_t)t * D;
                #pragma unroll
                for (int ni = 0; ni < 8; ni++) {
                    int nc = n0 + wn * 64 + ni * 8 + (lane & 3) * 2;
                    atomicAdd(orow + nc,     w * acc[mi][ni][rr * 2 + 0]);
                    atomicAdd(orow + nc + 1, w * acc[mi][ni][rr * 2 + 1]);
                }
            }
        }
    }
}

// ---------------- launch ----------------
extern "C" void kernel_launch(void* const* d_in, const int* in_sizes, int n_in,
                              void* d_out, int out_size) {
    const float* x      = (const float*)d_in[0];
    const float* router = (const float*)d_in[1];
    const float* w13    = (const float*)d_in[2];
    const float* w2     = (const float*)d_in[3];
    float* out = (float*)d_out;

    int T = in_sizes[0] / D;   // 8192

    init_kernel<<<1024, 256>>>(out, out_size);
    router_kernel<<<(T + 31) / 32, 256>>>(x, router, T);
    offsets_kernel<<<1, 32>>>();

    int mt = MAXCNT / 128;   // 32 m-tiles per expert (48-sigma bound)
    gemm1_kernel<<<dim3(MOED / 64, mt, E), 256>>>(x, w13);
    gemm2_kernel<<<dim3(D / 128, mt, E), 256>>>(w2, out);
}

// round 10
// speedup vs baseline: 1.1428x; 1.1428x over previous
#include <cuda_runtime.h>
#include <cuda_bf16.h>
#include <math.h>
#include <stdint.h>

// ---------------- problem constants ----------------
#define D        1024
#define E        8
#define MOED     2048
#define MAXROWS  16384
#define PADROWS  (MAXROWS + 256)
#define MAXCNT   4096      // per-expert row bound (mean 2048, sigma ~42; 48-sigma margin)

#define BK       16        // k elems per pipeline stage
#define ARS      48        // A smem row stride (16 bf16 = 32B + 16 pad)
#define BRS      272       // B smem row stride (128 bf16 = 256B + 16 pad)
#define AH_OFF   0
#define AL_OFF   6144
#define BH_OFF   12288
#define BL_OFF   16640
#define STAGE    20992
#define SM_BYTES (2 * STAGE)   // 41984 <= 48K static limit

// ---------------- device scratch (proven ~137 MB budget) ----------------
__device__ int   g_count[E];
__device__ int   g_offset[E];
__device__ int   g_tokens[E][MAXROWS];
__device__ float g_weights[E][MAXROWS];
__device__ __align__(256) __nv_bfloat16 g_hid_hi[(size_t)PADROWS * MOED];
__device__ __align__(256) __nv_bfloat16 g_hid_lo[(size_t)PADROWS * MOED];

// ---------------- helpers ----------------
__device__ __forceinline__ uint32_t smem_u32(const void* p) {
    uint32_t a;
    asm("{ .reg .u64 t; cvta.to.shared.u64 t, %1; cvt.u32.u64 %0, t; }" : "=r"(a) : "l"(p));
    return a;
}
__device__ __forceinline__ void ldsm4(uint32_t* r, uint32_t addr) {
    asm volatile("ldmatrix.sync.aligned.m8n8.x4.shared.b16 {%0,%1,%2,%3}, [%4];"
        : "=r"(r[0]), "=r"(r[1]), "=r"(r[2]), "=r"(r[3]) : "r"(addr));
}
__device__ __forceinline__ void ldsm4t(uint32_t* r, uint32_t addr) {
    asm volatile("ldmatrix.sync.aligned.m8n8.x4.trans.shared.b16 {%0,%1,%2,%3}, [%4];"
        : "=r"(r[0]), "=r"(r[1]), "=r"(r[2]), "=r"(r[3]) : "r"(addr));
}
__device__ __forceinline__ void mma16816(float* c, const uint32_t* a, uint32_t b0, uint32_t b1) {
    asm volatile("mma.sync.aligned.m16n8k16.row.col.f32.bf16.bf16.f32 "
        "{%0,%1,%2,%3}, {%4,%5,%6,%7}, {%8,%9}, {%0,%1,%2,%3};"
        : "+f"(c[0]), "+f"(c[1]), "+f"(c[2]), "+f"(c[3])
        : "r"(a[0]), "r"(a[1]), "r"(a[2]), "r"(a[3]), "r"(b0), "r"(b1));
}
__device__ __forceinline__ uint32_t pack2(float a, float b, uint32_t& lo) {
    __nv_bfloat16 ha = __float2bfloat16(a);
    __nv_bfloat16 hb = __float2bfloat16(b);
    __nv_bfloat16 la = __float2bfloat16(a - __bfloat162float(ha));
    __nv_bfloat16 lb = __float2bfloat16(b - __bfloat162float(hb));
    lo = (uint32_t)__bfloat16_as_ushort(la) | ((uint32_t)__bfloat16_as_ushort(lb) << 16);
    return (uint32_t)__bfloat16_as_ushort(ha) | ((uint32_t)__bfloat16_as_ushort(hb) << 16);
}
__device__ __forceinline__ void cvt8(float4 v0, float4 v1, uint4& hi, uint4& lo) {
    uint32_t l0, l1, l2, l3;
    uint32_t h0 = pack2(v0.x, v0.y, l0);
    uint32_t h1 = pack2(v0.z, v0.w, l1);
    uint32_t h2 = pack2(v1.x, v1.y, l2);
    uint32_t h3 = pack2(v1.z, v1.w, l3);
    hi = make_uint4(h0, h1, h2, h3);
    lo = make_uint4(l0, l1, l2, l3);
}

// ---------------- init ----------------
__global__ void init_kernel(float* __restrict__ out, int n) {
    int i = blockIdx.x * blockDim.x + threadIdx.x;
    if (i < E) g_count[i] = 0;
    for (; i < n; i += gridDim.x * blockDim.x) out[i] = 0.0f;
}

// ---------------- router (proven, verbatim) ----------------
__global__ void router_kernel(const float* __restrict__ x,
                              const float* __restrict__ router, int T) {
    __shared__ float s_r[D * E];
    __shared__ float s_logits[32][E];
    int tid = threadIdx.x;
    for (int i = tid; i < D * E; i += 256) s_r[i] = router[i];
    __syncthreads();

    int tl = tid >> 3;
    int e  = tid & 7;
    int t  = blockIdx.x * 32 + tl;
    float acc = 0.0f;
    if (t < T) {
        const float* xr = x + (size_t)t * D;
        #pragma unroll 8
        for (int k = 0; k < D; k++) acc = fmaf(xr[k], s_r[k * E + e], acc);
    }
    s_logits[tl][e] = acc;
    __syncthreads();

    if (tid < 32) {
        int t2 = blockIdx.x * 32 + tid;
        if (t2 < T) {
            float* L = s_logits[tid];
            int e0 = 0; float l0 = L[0];
            #pragma unroll
            for (int i = 1; i < E; i++) if (L[i] > l0) { l0 = L[i]; e0 = i; }
            int e1 = -1; float l1 = -INFINITY;
            #pragma unroll
            for (int i = 0; i < E; i++) {
                if (i == e0) continue;
                if (L[i] > l1) { l1 = L[i]; e1 = i; }
            }
            float w0 = 1.0f / (1.0f + expf(l1 - l0));
            float w1 = 1.0f - w0;
            int s0 = atomicAdd(&g_count[e0], 1);
            g_tokens[e0][s0]  = t2;
            g_weights[e0][s0] = w0;
            int s1 = atomicAdd(&g_count[e1], 1);
            g_tokens[e1][s1]  = t2;
            g_weights[e1][s1] = w1;
        }
    }
}

__global__ void offsets_kernel() {
    if (threadIdx.x == 0) {
        int s = 0;
        #pragma unroll
        for (int i = 0; i < E; i++) { g_offset[i] = s; s += g_count[i]; }
    }
}

// ---------------- GEMM1: 128m x (64 gate + 64 up), double-buffered BK=16 ------
// (R8 mainloop, byte-identical)
__global__ void __launch_bounds__(256, 2) gemm1_kernel(const float* __restrict__ x,
                                                       const float* __restrict__ w13) {
    __shared__ __align__(16) char sm[SM_BYTES];
    __shared__ int s_tok[128];
    int e   = blockIdx.z;
    int cnt = g_count[e];
    int m0  = blockIdx.y * 128;
    if (m0 >= cnt) return;
    int n0  = blockIdx.x * 64;
    int off = g_offset[e];
    int tid = threadIdx.x, wid = tid >> 5, lane = tid & 31;

    if (tid < 128) {
        int m = m0 + tid;
        s_tok[tid] = g_tokens[e][(m < cnt) ? m : (cnt - 1)];
    }
    __syncthreads();

    int arow = tid >> 1, akh = tid & 1;
    const float* aptr = x + (size_t)s_tok[arow] * D + akh * 8;
    uint32_t a_sdst = (uint32_t)(arow * ARS + akh * 16);
    int brow = tid >> 4, bc = tid & 15;
    int c8 = bc * 8;
    int ncol = (c8 < 64) ? (n0 + c8) : (MOED + n0 + (c8 - 64));
    const float* bptr = w13 + ((size_t)e * D + brow) * (2 * MOED) + ncol;
    uint32_t b_sdst = (uint32_t)(BH_OFF + brow * BRS + bc * 16);

    float accg[2][4][4], accu[2][4][4];
    #pragma unroll
    for (int i = 0; i < 2; i++)
        #pragma unroll
        for (int j = 0; j < 4; j++)
            #pragma unroll
            for (int q = 0; q < 4; q++) { accg[i][j][q] = 0.0f; accu[i][j][q] = 0.0f; }

    int wm = wid >> 1, wn = wid & 1;
    int lr = lane & 15, lh16 = (lane >> 4) << 4;
    int btr = ((lane >> 3) & 1) * 8 + (lane & 7);
    uint32_t sb = smem_u32(sm);

    float4 stgA[2], stgB[2];

    stgA[0] = *reinterpret_cast<const float4*>(aptr);
    stgA[1] = *reinterpret_cast<const float4*>(aptr + 4);
    stgB[0] = *reinterpret_cast<const float4*>(bptr);
    stgB[1] = *reinterpret_cast<const float4*>(bptr + 4);
    {
        uint4 hi, lo;
        cvt8(stgA[0], stgA[1], hi, lo);
        *reinterpret_cast<uint4*>(sm + a_sdst) = hi;
        *reinterpret_cast<uint4*>(sm + a_sdst + AL_OFF) = lo;
        cvt8(stgB[0], stgB[1], hi, lo);
        *reinterpret_cast<uint4*>(sm + b_sdst) = hi;
        *reinterpret_cast<uint4*>(sm + b_sdst + (BL_OFF - BH_OFF)) = lo;
    }
    stgA[0] = *reinterpret_cast<const float4*>(aptr + BK);
    stgA[1] = *reinterpret_cast<const float4*>(aptr + BK + 4);
    stgB[0] = *reinterpret_cast<const float4*>(bptr + (size_t)BK * (2 * MOED));
    stgB[1] = *reinterpret_cast<const float4*>(bptr + (size_t)BK * (2 * MOED) + 4);
    __syncthreads();

    const int KT = D / BK;   // 64
    for (int kt = 0; kt < KT; kt++) {
        int nbuf = (kt + 1) & 1;
        if (kt + 1 < KT) {
            uint4 hi, lo;
            cvt8(stgA[0], stgA[1], hi, lo);
            *reinterpret_cast<uint4*>(sm + nbuf * STAGE + a_sdst) = hi;
            *reinterpret_cast<uint4*>(sm + nbuf * STAGE + a_sdst + AL_OFF) = lo;
            cvt8(stgB[0], stgB[1], hi, lo);
            *reinterpret_cast<uint4*>(sm + nbuf * STAGE + b_sdst) = hi;
            *reinterpret_cast<uint4*>(sm + nbuf * STAGE + b_sdst + (BL_OFF - BH_OFF)) = lo;
        }
        if (kt + 2 < KT) {
            stgA[0] = *reinterpret_cast<const float4*>(aptr + (kt + 2) * BK);
            stgA[1] = *reinterpret_cast<const float4*>(aptr + (kt + 2) * BK + 4);
            stgB[0] = *reinterpret_cast<const float4*>(bptr + (size_t)(kt + 2) * BK * (2 * MOED));
            stgB[1] = *reinterpret_cast<const float4*>(bptr + (size_t)(kt + 2) * BK * (2 * MOED) + 4);
        }

        uint32_t bb = sb + (kt & 1) * STAGE;
        uint32_t aH = bb + (uint32_t)(wm * 32 + lr) * ARS + lh16;
        uint32_t aL = aH + AL_OFF;
        uint32_t bH = bb + BH_OFF + (uint32_t)btr * BRS + wn * 64 + lh16;
        uint32_t bL = bH + (BL_OFF - BH_OFF);

        uint32_t ah[2][4], al[2][4];
        #pragma unroll
        for (int mi = 0; mi < 2; mi++) {
            ldsm4(ah[mi], aH + mi * (16 * ARS));
            ldsm4(al[mi], aL + mi * (16 * ARS));
        }
        #pragma unroll
        for (int half = 0; half < 2; half++) {
            uint32_t gh[4], gl[4], uh[4], ul[4];
            uint32_t boff = (uint32_t)(half * 32);
            ldsm4t(gh, bH + boff);
            ldsm4t(gl, bL + boff);
            ldsm4t(uh, bH + boff + 128);
            ldsm4t(ul, bL + boff + 128);
            #pragma unroll
            for (int r = 0; r < 2; r++) {
                int ni = half * 2 + r;
                #pragma unroll
                for (int mi = 0; mi < 2; mi++) {
                    mma16816(accg[mi][ni], ah[mi], gh[2 * r], gh[2 * r + 1]);
                    mma16816(accg[mi][ni], ah[mi], gl[2 * r], gl[2 * r + 1]);
                    mma16816(accg[mi][ni], al[mi], gh[2 * r], gh[2 * r + 1]);
                    mma16816(accu[mi][ni], ah[mi], uh[2 * r], uh[2 * r + 1]);
                    mma16816(accu[mi][ni], ah[mi], ul[2 * r], ul[2 * r + 1]);
                    mma16816(accu[mi][ni], al[mi], uh[2 * r], uh[2 * r + 1]);
                }
            }
        }
        __syncthreads();
    }

    // epilogue: SwiGLU, split in-register, store bf16 hi/lo hidden
    #pragma unroll
    for (int mi = 0; mi < 2; mi++) {
        #pragma unroll
        for (int rr = 0; rr < 2; rr++) {
            int ml = wm * 32 + mi * 16 + (lane >> 2) + rr * 8;
            if (m0 + ml < cnt) {
                size_t rb = (size_t)(off + m0 + ml) * MOED + n0 + wn * 32;
                #pragma unroll
                for (int ni = 0; ni < 4; ni++) {
                    int nc = ni * 8 + (lane & 3) * 2;
                    float g0 = accg[mi][ni][rr * 2 + 0], g1 = accg[mi][ni][rr * 2 + 1];
                    float u0 = accu[mi][ni][rr * 2 + 0], u1 = accu[mi][ni][rr * 2 + 1];
                    float h0 = u0 * g0 / (1.0f + __expf(-g0));
                    float h1 = u1 * g1 / (1.0f + __expf(-g1));
                    uint32_t lo;
                    uint32_t hi = pack2(h0, h1, lo);
                    *reinterpret_cast<uint32_t*>(g_hid_hi + rb + nc) = hi;
                    *reinterpret_cast<uint32_t*>(g_hid_lo + rb + nc) = lo;
                }
            }
        }
    }
}

// ---------------- GEMM2: 128m x 128n, double-buffered BK=16 -------------------
// (R8 mainloop, byte-identical)
__global__ void __launch_bounds__(256, 2) gemm2_kernel(const float* __restrict__ w2,
                                                       float* __restrict__ out) {
    __shared__ __align__(16) char sm[SM_BYTES];
    int e   = blockIdx.z;
    int cnt = g_count[e];
    int m0  = blockIdx.y * 128;
    if (m0 >= cnt) return;
    int n0  = blockIdx.x * 128;
    int off = g_offset[e];
    int tid = threadIdx.x, wid = tid >> 5, lane = tid & 31;

    int arow = tid >> 1, akh = tid & 1;
    const __nv_bfloat16* aH_src = g_hid_hi + (size_t)(off + m0 + arow) * MOED + akh * 8;
    const __nv_bfloat16* aL_src = g_hid_lo + (size_t)(off + m0 + arow) * MOED + akh * 8;
    uint32_t a_sdst = (uint32_t)(arow * ARS + akh * 16);
    int brow = tid >> 4, bc = tid & 15;
    const float* bptr = w2 + ((size_t)e * MOED + brow) * D + n0 + bc * 8;
    uint32_t b_sdst = (uint32_t)(BH_OFF + brow * BRS + bc * 16);

    float acc[2][8][4];
    #pragma unroll
    for (int i = 0; i < 2; i++)
        #pragma unroll
        for (int j = 0; j < 8; j++)
            #pragma unroll
            for (int q = 0; q < 4; q++) acc[i][j][q] = 0.0f;

    int wm = wid >> 1, wn = wid & 1;
    int lr = lane & 15, lh16 = (lane >> 4) << 4;
    int btr = ((lane >> 3) & 1) * 8 + (lane & 7);
    uint32_t sb = smem_u32(sm);

    uint4 stgAH, stgAL;
    float4 stgB[2];

    stgAH = *reinterpret_cast<const uint4*>(aH_src);
    stgAL = *reinterpret_cast<const uint4*>(aL_src);
    stgB[0] = *reinterpret_cast<const float4*>(bptr);
    stgB[1] = *reinterpret_cast<const float4*>(bptr + 4);
    {
        *reinterpret_cast<uint4*>(sm + a_sdst) = stgAH;
        *reinterpret_cast<uint4*>(sm + a_sdst + AL_OFF) = stgAL;
        uint4 hi, lo;
        cvt8(stgB[0], stgB[1], hi, lo);
        *reinterpret_cast<uint4*>(sm + b_sdst) = hi;
        *reinterpret_cast<uint4*>(sm + b_sdst + (BL_OFF - BH_OFF)) = lo;
    }
    stgAH = *reinterpret_cast<const uint4*>(aH_src + BK);
    stgAL = *reinterpret_cast<const uint4*>(aL_src + BK);
    stgB[0] = *reinterpret_cast<const float4*>(bptr + (size_t)BK * D);
    stgB[1] = *reinterpret_cast<const float4*>(bptr + (size_t)BK * D + 4);
    __syncthreads();

    const int KT = MOED / BK;   // 128
    for (int kt = 0; kt < KT; kt++) {
        int nbuf = (kt + 1) & 1;
        if (kt + 1 < KT) {
            *reinterpret_cast<uint4*>(sm + nbuf * STAGE + a_sdst) = stgAH;
            *reinterpret_cast<uint4*>(sm + nbuf * STAGE + a_sdst + AL_OFF) = stgAL;
            uint4 hi, lo;
            cvt8(stgB[0], stgB[1], hi, lo);
            *reinterpret_cast<uint4*>(sm + nbuf * STAGE + b_sdst) = hi;
            *reinterpret_cast<uint4*>(sm + nbuf * STAGE + b_sdst + (BL_OFF - BH_OFF)) = lo;
        }
        if (kt + 2 < KT) {
            stgAH = *reinterpret_cast<const uint4*>(aH_src + (kt + 2) * BK);
            stgAL = *reinterpret_cast<const uint4*>(aL_src + (kt + 2) * BK);
            stgB[0] = *reinterpret_cast<const float4*>(bptr + (size_t)(kt + 2) * BK * D);
            stgB[1] = *reinterpret_cast<const float4*>(bptr + (size_t)(kt + 2) * BK * D + 4);
        }

        uint32_t bb = sb + (kt & 1) * STAGE;
        uint32_t aH = bb + (uint32_t)(wm * 32 + lr) * ARS + lh16;
        uint32_t aL = aH + AL_OFF;
        uint32_t bH = bb + BH_OFF + (uint32_t)btr * BRS + wn * 128 + lh16;
        uint32_t bL = bH + (BL_OFF - BH_OFF);

        uint32_t ah[2][4], al[2][4];
        #pragma unroll
        for (int mi = 0; mi < 2; mi++) {
            ldsm4(ah[mi], aH + mi * (16 * ARS));
            ldsm4(al[mi], aL + mi * (16 * ARS));
        }
        #pragma unroll
        for (int half = 0; half < 4; half++) {
            uint32_t bh[4], bl[4];
            uint32_t boff = (uint32_t)(half * 32);
            ldsm4t(bh, bH + boff);
            ldsm4t(bl, bL + boff);
            #pragma unroll
            for (int r = 0; r < 2; r++) {
                int ni = half * 2 + r;
                #pragma unroll
                for (int mi = 0; mi < 2; mi++) {
                    mma16816(acc[mi][ni], ah[mi], bh[2 * r], bh[2 * r + 1]);
                    mma16816(acc[mi][ni], ah[mi], bl[2 * r], bl[2 * r + 1]);
                    mma16816(acc[mi][ni], al[mi], bh[2 * r], bh[2 * r + 1]);
                }
            }
        }
        __syncthreads();
    }

    // epilogue: weighted scatter-add (exactly 2 adds per out element)
    #pragma unroll
    for (int mi = 0; mi < 2; mi++) {
        #pragma unroll
        for (int rr = 0; rr < 2; rr++) {
            int ml = wm * 32 + mi * 16 + (lane >> 2) + rr * 8;
            if (m0 + ml < cnt) {
                int   t = g_tokens[e][m0 + ml];
                float w = g_weights[e][m0 + ml];
                float* orow = out + (size_t)t * D;
                #pragma unroll
                for (int ni = 0; ni < 8; ni++) {
                    int nc = n0 + wn * 64 + ni * 8 + (lane & 3) * 2;
                    atomicAdd(orow + nc,     w * acc[mi][ni][rr * 2 + 0]);
                    atomicAdd(orow + nc + 1, w * acc[mi][ni][rr * 2 + 1]);
                }
            }
        }
    }
}

// ---------------- launch ----------------
extern "C" void kernel_launch(void* const* d_in, const int* in_sizes, int n_in,
                              void* d_out, int out_size) {
    const float* x      = (const float*)d_in[0];
    const float* router = (const float*)d_in[1];
    const float* w13    = (const float*)d_in[2];
    const float* w2     = (const float*)d_in[3];
    float* out = (float*)d_out;

    int T = in_sizes[0] / D;   // 8192

    init_kernel<<<1024, 256>>>(out, out_size);
    router_kernel<<<(T + 31) / 32, 256>>>(x, router, T);
    offsets_kernel<<<1, 32>>>();

    int mt = MAXCNT / 128;   // 32 m-tiles per expert (48-sigma bound)
    gemm1_kernel<<<dim3(MOED / 64, mt, E), 256>>>(x, w13);
    gemm2_kernel<<<dim3(D / 128, mt, E), 256>>>(w2, out);
}

// round 11
// speedup vs baseline: 1.2711x; 1.1122x over previous
#include <cuda_runtime.h>
#include <cuda_bf16.h>
#include <math.h>
#include <stdint.h>

// ---------------- problem constants ----------------
#define D        1024
#define E        8
#define MOED     2048
#define T_TOK    8192
#define MAXROWS  16384
#define PADROWS  (MAXROWS + 256)
#define MAXCNT   4096      // per-expert row bound (mean 2048, sigma ~42; 48-sigma margin)

#define BK       16        // k elems per pipeline stage
#define ARS      48        // A smem row stride (16 bf16 = 32B + 16 pad)
#define BRS      272       // B smem row stride (128 bf16 = 256B + 16 pad)
#define AH_OFF   0
#define AL_OFF   6144
#define BH_OFF   12288
#define BL_OFF   16640
#define STAGE    20992
#define SM_BYTES (2 * STAGE)   // 41984 <= 48K static limit

// ---------------- device scratch (~171 MB total; tests the budget hypothesis) --
__device__ int   g_count[E];
__device__ int   g_offset[E];
__device__ int   g_tokens[E][MAXROWS];
__device__ float g_weights[E][MAXROWS];
__device__ __align__(256) __nv_bfloat16 g_x_hi[(size_t)T_TOK * D];     // 16.8 MB
__device__ __align__(256) __nv_bfloat16 g_x_lo[(size_t)T_TOK * D];     // 16.8 MB
__device__ __align__(256) __nv_bfloat16 g_hid_hi[(size_t)PADROWS * MOED];
__device__ __align__(256) __nv_bfloat16 g_hid_lo[(size_t)PADROWS * MOED];

// ---------------- helpers ----------------
__device__ __forceinline__ uint32_t smem_u32(const void* p) {
    uint32_t a;
    asm("{ .reg .u64 t; cvta.to.shared.u64 t, %1; cvt.u32.u64 %0, t; }" : "=r"(a) : "l"(p));
    return a;
}
__device__ __forceinline__ void cpasync16(uint32_t s, const void* g) {
    asm volatile("cp.async.cg.shared.global [%0], [%1], 16;" :: "r"(s), "l"(g));
}
#define CP_COMMIT() asm volatile("cp.async.commit_group;" ::: "memory")
#define CP_WAIT0()  asm volatile("cp.async.wait_group 0;"  ::: "memory")

__device__ __forceinline__ void ldsm4(uint32_t* r, uint32_t addr) {
    asm volatile("ldmatrix.sync.aligned.m8n8.x4.shared.b16 {%0,%1,%2,%3}, [%4];"
        : "=r"(r[0]), "=r"(r[1]), "=r"(r[2]), "=r"(r[3]) : "r"(addr));
}
__device__ __forceinline__ void ldsm4t(uint32_t* r, uint32_t addr) {
    asm volatile("ldmatrix.sync.aligned.m8n8.x4.trans.shared.b16 {%0,%1,%2,%3}, [%4];"
        : "=r"(r[0]), "=r"(r[1]), "=r"(r[2]), "=r"(r[3]) : "r"(addr));
}
__device__ __forceinline__ void mma16816(float* c, const uint32_t* a, uint32_t b0, uint32_t b1) {
    asm volatile("mma.sync.aligned.m16n8k16.row.col.f32.bf16.bf16.f32 "
        "{%0,%1,%2,%3}, {%4,%5,%6,%7}, {%8,%9}, {%0,%1,%2,%3};"
        : "+f"(c[0]), "+f"(c[1]), "+f"(c[2]), "+f"(c[3])
        : "r"(a[0]), "r"(a[1]), "r"(a[2]), "r"(a[3]), "r"(b0), "r"(b1));
}
__device__ __forceinline__ uint32_t pack2(float a, float b, uint32_t& lo) {
    __nv_bfloat16 ha = __float2bfloat16(a);
    __nv_bfloat16 hb = __float2bfloat16(b);
    __nv_bfloat16 la = __float2bfloat16(a - __bfloat162float(ha));
    __nv_bfloat16 lb = __float2bfloat16(b - __bfloat162float(hb));
    lo = (uint32_t)__bfloat16_as_ushort(la) | ((uint32_t)__bfloat16_as_ushort(lb) << 16);
    return (uint32_t)__bfloat16_as_ushort(ha) | ((uint32_t)__bfloat16_as_ushort(hb) << 16);
}
__device__ __forceinline__ void cvt8(float4 v0, float4 v1, uint4& hi, uint4& lo) {
    uint32_t l0, l1, l2, l3;
    uint32_t h0 = pack2(v0.x, v0.y, l0);
    uint32_t h1 = pack2(v0.z, v0.w, l1);
    uint32_t h2 = pack2(v1.x, v1.y, l2);
    uint32_t h3 = pack2(v1.z, v1.w, l3);
    hi = make_uint4(h0, h1, h2, h3);
    lo = make_uint4(l0, l1, l2, l3);
}

// ---------------- init ----------------
__global__ void init_kernel(float* __restrict__ out, int n) {
    int i = blockIdx.x * blockDim.x + threadIdx.x;
    if (i < E) g_count[i] = 0;
    for (; i < n; i += gridDim.x * blockDim.x) out[i] = 0.0f;
}

// ---------------- x split: fp32 -> bf16 hi/lo (token order, no gather) --------
__global__ void xsplit_kernel(const float* __restrict__ x) {
    size_t i = ((size_t)blockIdx.x * blockDim.x + threadIdx.x) * 8;
    float4 v0 = *reinterpret_cast<const float4*>(x + i);
    float4 v1 = *reinterpret_cast<const float4*>(x + i + 4);
    uint4 hi, lo;
    cvt8(v0, v1, hi, lo);
    *reinterpret_cast<uint4*>(g_x_hi + i) = hi;
    *reinterpret_cast<uint4*>(g_x_lo + i) = lo;
}

// ---------------- router (proven, verbatim) ----------------
__global__ void router_kernel(const float* __restrict__ x,
                              const float* __restrict__ router, int T) {
    __shared__ float s_r[D * E];
    __shared__ float s_logits[32][E];
    int tid = threadIdx.x;
    for (int i = tid; i < D * E; i += 256) s_r[i] = router[i];
    __syncthreads();

    int tl = tid >> 3;
    int e  = tid & 7;
    int t  = blockIdx.x * 32 + tl;
    float acc = 0.0f;
    if (t < T) {
        const float* xr = x + (size_t)t * D;
        #pragma unroll 8
        for (int k = 0; k < D; k++) acc = fmaf(xr[k], s_r[k * E + e], acc);
    }
    s_logits[tl][e] = acc;
    __syncthreads();

    if (tid < 32) {
        int t2 = blockIdx.x * 32 + tid;
        if (t2 < T) {
            float* L = s_logits[tid];
            int e0 = 0; float l0 = L[0];
            #pragma unroll
            for (int i = 1; i < E; i++) if (L[i] > l0) { l0 = L[i]; e0 = i; }
            int e1 = -1; float l1 = -INFINITY;
            #pragma unroll
            for (int i = 0; i < E; i++) {
                if (i == e0) continue;
                if (L[i] > l1) { l1 = L[i]; e1 = i; }
            }
            float w0 = 1.0f / (1.0f + expf(l1 - l0));
            float w1 = 1.0f - w0;
            int s0 = atomicAdd(&g_count[e0], 1);
            g_tokens[e0][s0]  = t2;
            g_weights[e0][s0] = w0;
            int s1 = atomicAdd(&g_count[e1], 1);
            g_tokens[e1][s1]  = t2;
            g_weights[e1][s1] = w1;
        }
    }
}

__global__ void offsets_kernel() {
    if (threadIdx.x == 0) {
        int s = 0;
        #pragma unroll
        for (int i = 0; i < E; i++) { g_offset[i] = s; s += g_count[i]; }
    }
}

// ---------------- GEMM1: 128m x (64 gate + 64 up), cp.async A, BK=16 ----------
__global__ void __launch_bounds__(256, 2) gemm1_kernel(const float* __restrict__ w13) {
    __shared__ __align__(16) char sm[SM_BYTES];
    __shared__ int s_tok[128];
    int e   = blockIdx.z;
    int cnt = g_count[e];
    int m0  = blockIdx.y * 128;
    if (m0 >= cnt) return;
    int n0  = blockIdx.x * 64;
    int off = g_offset[e];
    int tid = threadIdx.x, wid = tid >> 5, lane = tid & 31;

    if (tid < 128) {
        int m = m0 + tid;
        s_tok[tid] = g_tokens[e][(m < cnt) ? m : (cnt - 1)];
    }
    __syncthreads();

    // A: pre-split bf16 x, via cp.async (16B per thread per plane)
    int arow = tid >> 1, akh = tid & 1;
    const __nv_bfloat16* aHsrc = g_x_hi + (size_t)s_tok[arow] * D + akh * 8;
    const __nv_bfloat16* aLsrc = g_x_lo + (size_t)s_tok[arow] * D + akh * 8;
    uint32_t a_off = (uint32_t)(arow * ARS + akh * 16);
    // B: fp32 w13, reg-staged + cvt (proven)
    int brow = tid >> 4, bc = tid & 15;
    int c8 = bc * 8;
    int ncol = (c8 < 64) ? (n0 + c8) : (MOED + n0 + (c8 - 64));
    const float* bptr = w13 + ((size_t)e * D + brow) * (2 * MOED) + ncol;
    uint32_t b_sdst = (uint32_t)(BH_OFF + brow * BRS + bc * 16);

    float accg[2][4][4], accu[2][4][4];
    #pragma unroll
    for (int i = 0; i < 2; i++)
        #pragma unroll
        for (int j = 0; j < 4; j++)
            #pragma unroll
            for (int q = 0; q < 4; q++) { accg[i][j][q] = 0.0f; accu[i][j][q] = 0.0f; }

    int wm = wid >> 1, wn = wid & 1;
    int lr = lane & 15, lh16 = (lane >> 4) << 4;
    int btr = ((lane >> 3) & 1) * 8 + (lane & 7);
    uint32_t sb = smem_u32(sm);

    float4 stgB[2];

    // prologue: stage 0
    cpasync16(sb + a_off, aHsrc);
    cpasync16(sb + a_off + AL_OFF, aLsrc);
    stgB[0] = *reinterpret_cast<const float4*>(bptr);
    stgB[1] = *reinterpret_cast<const float4*>(bptr + 4);
    {
        uint4 hi, lo;
        cvt8(stgB[0], stgB[1], hi, lo);
        *reinterpret_cast<uint4*>(sm + b_sdst) = hi;
        *reinterpret_cast<uint4*>(sm + b_sdst + (BL_OFF - BH_OFF)) = lo;
    }
    CP_COMMIT();
    stgB[0] = *reinterpret_cast<const float4*>(bptr + (size_t)BK * (2 * MOED));
    stgB[1] = *reinterpret_cast<const float4*>(bptr + (size_t)BK * (2 * MOED) + 4);
    CP_WAIT0();
    __syncthreads();

    const int KT = D / BK;   // 64
    for (int kt = 0; kt < KT; kt++) {
        int nbuf = (kt + 1) & 1;
        if (kt + 1 < KT) {
            cpasync16(sb + nbuf * STAGE + a_off, aHsrc + (kt + 1) * BK);
            cpasync16(sb + nbuf * STAGE + a_off + AL_OFF, aLsrc + (kt + 1) * BK);
            uint4 hi, lo;
            cvt8(stgB[0], stgB[1], hi, lo);
            *reinterpret_cast<uint4*>(sm + nbuf * STAGE + b_sdst) = hi;
            *reinterpret_cast<uint4*>(sm + nbuf * STAGE + b_sdst + (BL_OFF - BH_OFF)) = lo;
            CP_COMMIT();
        }
        if (kt + 2 < KT) {
            stgB[0] = *reinterpret_cast<const float4*>(bptr + (size_t)(kt + 2) * BK * (2 * MOED));
            stgB[1] = *reinterpret_cast<const float4*>(bptr + (size_t)(kt + 2) * BK * (2 * MOED) + 4);
        }

        uint32_t bb = sb + (kt & 1) * STAGE;
        uint32_t aH = bb + (uint32_t)(wm * 32 + lr) * ARS + lh16;
        uint32_t aL = aH + AL_OFF;
        uint32_t bH = bb + BH_OFF + (uint32_t)btr * BRS + wn * 64 + lh16;
        uint32_t bL = bH + (BL_OFF - BH_OFF);

        uint32_t ah[2][4], al[2][4];
        #pragma unroll
        for (int mi = 0; mi < 2; mi++) {
            ldsm4(ah[mi], aH + mi * (16 * ARS));
            ldsm4(al[mi], aL + mi * (16 * ARS));
        }
        #pragma unroll
        for (int half = 0; half < 2; half++) {
            uint32_t gh[4], gl[4], uh[4], ul[4];
            uint32_t boff = (uint32_t)(half * 32);
            ldsm4t(gh, bH + boff);
            ldsm4t(gl, bL + boff);
            ldsm4t(uh, bH + boff + 128);
            ldsm4t(ul, bL + boff + 128);
            #pragma unroll
            for (int r = 0; r < 2; r++) {
                int ni = half * 2 + r;
                #pragma unroll
                for (int mi = 0; mi < 2; mi++) {
                    mma16816(accg[mi][ni], ah[mi], gh[2 * r], gh[2 * r + 1]);
                    mma16816(accg[mi][ni], ah[mi], gl[2 * r], gl[2 * r + 1]);
                    mma16816(accg[mi][ni], al[mi], gh[2 * r], gh[2 * r + 1]);
                    mma16816(accu[mi][ni], ah[mi], uh[2 * r], uh[2 * r + 1]);
                    mma16816(accu[mi][ni], ah[mi], ul[2 * r], ul[2 * r + 1]);
                    mma16816(accu[mi][ni], al[mi], uh[2 * r], uh[2 * r + 1]);
                }
            }
        }
        CP_WAIT0();
        __syncthreads();
    }

    // epilogue: SwiGLU, split in-register, store bf16 hi/lo hidden
    #pragma unroll
    for (int mi = 0; mi < 2; mi++) {
        #pragma unroll
        for (int rr = 0; rr < 2; rr++) {
            int ml = wm * 32 + mi * 16 + (lane >> 2) + rr * 8;
            if (m0 + ml < cnt) {
                size_t rb = (size_t)(off + m0 + ml) * MOED + n0 + wn * 32;
                #pragma unroll
                for (int ni = 0; ni < 4; ni++) {
                    int nc = ni * 8 + (lane & 3) * 2;
                    float g0 = accg[mi][ni][rr * 2 + 0], g1 = accg[mi][ni][rr * 2 + 1];
                    float u0 = accu[mi][ni][rr * 2 + 0], u1 = accu[mi][ni][rr * 2 + 1];
                    float h0 = u0 * g0 / (1.0f + __expf(-g0));
                    float h1 = u1 * g1 / (1.0f + __expf(-g1));
                    uint32_t lo;
                    uint32_t hi = pack2(h0, h1, lo);
                    *reinterpret_cast<uint32_t*>(g_hid_hi + rb + nc) = hi;
                    *reinterpret_cast<uint32_t*>(g_hid_lo + rb + nc) = lo;
                }
            }
        }
    }
}

// ---------------- GEMM2: 128m x 128n, cp.async A, BK=16 -----------------------
__global__ void __launch_bounds__(256, 2) gemm2_kernel(const float* __restrict__ w2,
                                                       float* __restrict__ out) {
    __shared__ __align__(16) char sm[SM_BYTES];
    int e   = blockIdx.z;
    int cnt = g_count[e];
    int m0  = blockIdx.y * 128;
    if (m0 >= cnt) return;
    int n0  = blockIdx.x * 128;
    int off = g_offset[e];
    int tid = threadIdx.x, wid = tid >> 5, lane = tid & 31;

    int arow = tid >> 1, akh = tid & 1;
    const __nv_bfloat16* aHsrc = g_hid_hi + (size_t)(off + m0 + arow) * MOED + akh * 8;
    const __nv_bfloat16* aLsrc = g_hid_lo + (size_t)(off + m0 + arow) * MOED + akh * 8;
    uint32_t a_off = (uint32_t)(arow * ARS + akh * 16);
    int brow = tid >> 4, bc = tid & 15;
    const float* bptr = w2 + ((size_t)e * MOED + brow) * D + n0 + bc * 8;
    uint32_t b_sdst = (uint32_t)(BH_OFF + brow * BRS + bc * 16);

    float acc[2][8][4];
    #pragma unroll
    for (int i = 0; i < 2; i++)
        #pragma unroll
        for (int j = 0; j < 8; j++)
            #pragma unroll
            for (int q = 0; q < 4; q++) acc[i][j][q] = 0.0f;

    int wm = wid >> 1, wn = wid & 1;
    int lr = lane & 15, lh16 = (lane >> 4) << 4;
    int btr = ((lane >> 3) & 1) * 8 + (lane & 7);
    uint32_t sb = smem_u32(sm);

    float4 stgB[2];

    // prologue: stage 0
    cpasync16(sb + a_off, aHsrc);
    cpasync16(sb + a_off + AL_OFF, aLsrc);
    stgB[0] = *reinterpret_cast<const float4*>(bptr);
    stgB[1] = *reinterpret_cast<const float4*>(bptr + 4);
    {
        uint4 hi, lo;
        cvt8(stgB[0], stgB[1], hi, lo);
        *reinterpret_cast<uint4*>(sm + b_sdst) = hi;
        *reinterpret_cast<uint4*>(sm + b_sdst + (BL_OFF - BH_OFF)) = lo;
    }
    CP_COMMIT();
    stgB[0] = *reinterpret_cast<const float4*>(bptr + (size_t)BK * D);
    stgB[1] = *reinterpret_cast<const float4*>(bptr + (size_t)BK * D + 4);
    CP_WAIT0();
    __syncthreads();

    const int KT = MOED / BK;   // 128
    for (int kt = 0; kt < KT; kt++) {
        int nbuf = (kt + 1) & 1;
        if (kt + 1 < KT) {
            cpasync16(sb + nbuf * STAGE + a_off, aHsrc + (kt + 1) * BK);
            cpasync16(sb + nbuf * STAGE + a_off + AL_OFF, aLsrc + (kt + 1) * BK);
            uint4 hi, lo;
            cvt8(stgB[0], stgB[1], hi, lo);
            *reinterpret_cast<uint4*>(sm + nbuf * STAGE + b_sdst) = hi;
            *reinterpret_cast<uint4*>(sm + nbuf * STAGE + b_sdst + (BL_OFF - BH_OFF)) = lo;
            CP_COMMIT();
        }
        if (kt + 2 < KT) {
            stgB[0] = *reinterpret_cast<const float4*>(bptr + (size_t)(kt + 2) * BK * D);
            stgB[1] = *reinterpret_cast<const float4*>(bptr + (size_t)(kt + 2) * BK * D + 4);
        }

        uint32_t bb = sb + (kt & 1) * STAGE;
        uint32_t aH = bb + (uint32_t)(wm * 32 + lr) * ARS + lh16;
        uint32_t aL = aH + AL_OFF;
        uint32_t bH = bb + BH_OFF + (uint32_t)btr * BRS + wn * 128 + lh16;
        uint32_t bL = bH + (BL_OFF - BH_OFF);

        uint32_t ah[2][4], al[2][4];
        #pragma unroll
        for (int mi = 0; mi < 2; mi++) {
            ldsm4(ah[mi], aH + mi * (16 * ARS));
            ldsm4(al[mi], aL + mi * (16 * ARS));
        }
        #pragma unroll
        for (int half = 0; half < 4; half++) {
            uint32_t bh[4], bl[4];
            uint32_t boff = (uint32_t)(half * 32);
            ldsm4t(bh, bH + boff);
            ldsm4t(bl, bL + boff);
            #pragma unroll
            for (int r = 0; r < 2; r++) {
                int ni = half * 2 + r;
                #pragma unroll
                for (int mi = 0; mi < 2; mi++) {
                    mma16816(acc[mi][ni], ah[mi], bh[2 * r], bh[2 * r + 1]);
                    mma16816(acc[mi][ni], ah[mi], bl[2 * r], bl[2 * r + 1]);
                    mma16816(acc[mi][ni], al[mi], bh[2 * r], bh[2 * r + 1]);
                }
            }
        }
        CP_WAIT0();
        __syncthreads();
    }

    // epilogue: weighted scatter-add (exactly 2 adds per out element)
    #pragma unroll
    for (int mi = 0; mi < 2; mi++) {
        #pragma unroll
        for (int rr = 0; rr < 2; rr++) {
            int ml = wm * 32 + mi * 16 + (lane >> 2) + rr * 8;
            if (m0 + ml < cnt) {
                int   t = g_tokens[e][m0 + ml];
                float w = g_weights[e][m0 + ml];
                float* orow = out + (size_t)t * D;
                #pragma unroll
                for (int ni = 0; ni < 8; ni++) {
                    int nc = n0 + wn * 64 + ni * 8 + (lane & 3) * 2;
                    atomicAdd(orow + nc,     w * acc[mi][ni][rr * 2 + 0]);
                    atomicAdd(orow + nc + 1, w * acc[mi][ni][rr * 2 + 1]);
                }
            }
        }
    }
}

// ---------------- launch ----------------
extern "C" void kernel_launch(void* const* d_in, const int* in_sizes, int n_in,
                              void* d_out, int out_size) {
    const float* x      = (const float*)d_in[0];
    const float* router = (const float*)d_in[1];
    const float* w13    = (const float*)d_in[2];
    const float* w2     = (const float*)d_in[3];
    float* out = (float*)d_out;

    int T = in_sizes[0] / D;   // 8192

    init_kernel<<<1024, 256>>>(out, out_size);
    xsplit_kernel<<<(unsigned)((size_t)T * D / 8 / 256), 256>>>(x);
    router_kernel<<<(T + 31) / 32, 256>>>(x, router, T);
    offsets_kernel<<<1, 32>>>();

    int mt = MAXCNT / 128;   // 32 m-tiles per expert (48-sigma bound)
    gemm1_kernel<<<dim3(MOED / 64, mt, E), 256>>>(w13);
    gemm2_kernel<<<dim3(D / 128, mt, E), 256>>>(w2, out);
}